// round 1
// baseline (speedup 1.0000x reference)
#include <cuda_runtime.h>
#include <cuda_bf16.h>

#define BB 4
#define SS 4096
#define DD 512
#define HH 64

// Scratch for projected Q, K, V: [B*S, 64] each (4 MB each, 12 MB total).
__device__ float g_q[BB * SS * HH];
__device__ float g_k[BB * SS * HH];
__device__ float g_v[BB * SS * HH];

// XOR swizzle on float4 granularity: 64-row x 16-float4 tile.
// slot(row, c4) — conflict-free for all LDS.128 patterns used below.
__device__ __forceinline__ int swz(int r, int c4) {
    return (r << 4) | (c4 ^ ((r >> 2) & 7));
}

__device__ __forceinline__ float comp4(const float4& v, int cc) {
    return cc == 0 ? v.x : cc == 1 ? v.y : cc == 2 ? v.z : v.w;
}

// Load a 64-row x 16-float4 tile (global, row stride rs4 float4s) into swizzled smem.
// 256 threads, 4 float4 each. Coalesced: consecutive tid -> consecutive c4.
__device__ __forceinline__ void load_tile(float4* __restrict__ dst,
                                          const float4* __restrict__ src,
                                          int rs4, int tid) {
#pragma unroll
    for (int l = 0; l < 4; ++l) {
        int idx = tid + l * 256;
        int r = idx >> 4, c4 = idx & 15;
        dst[swz(r, c4)] = src[(size_t)r * rs4 + c4];
    }
}

// acc[4][4] += A_tile[64 x 64] * W_tile[64 x 64]
// A rows owned by ty (4 rows), W cols owned by tx (4 cols), reduction over 64.
// Per k4 step: 4 broadcast LDS.128 (A) + 4 conflict-free LDS.128 (W) + 64 FFMA.
__device__ __forceinline__ void gemm_tile(float (&acc)[4][4],
                                          const float4* __restrict__ A,
                                          const float4* __restrict__ Wt,
                                          int tx, int ty) {
#pragma unroll 4
    for (int k4 = 0; k4 < 16; ++k4) {
        float4 a[4];
#pragma unroll
        for (int i = 0; i < 4; ++i) a[i] = A[swz(4 * ty + i, k4)];
#pragma unroll
        for (int cc = 0; cc < 4; ++cc) {
            float4 w = Wt[swz(4 * k4 + cc, tx)];
#pragma unroll
            for (int i = 0; i < 4; ++i) {
                float av = comp4(a[i], cc);
                acc[i][0] += av * w.x;
                acc[i][1] += av * w.y;
                acc[i][2] += av * w.z;
                acc[i][3] += av * w.w;
            }
        }
    }
}

// ---------------------------------------------------------------------------
// Kernel 1: fused QKV projection.
// Grid: 256 blocks (64 rows each of the 16384 x-rows). Block: 256 threads.
// Each block computes a 64x64 tile of Q, K and V, reusing the x-tile 3x.
// ---------------------------------------------------------------------------
__global__ void __launch_bounds__(256, 2) qkv_kernel(
    const float* __restrict__ x,
    const float* __restrict__ Wq, const float* __restrict__ bq,
    const float* __restrict__ Wk, const float* __restrict__ bk,
    const float* __restrict__ Wv, const float* __restrict__ bv)
{
    __shared__ float4 Xs[1024];   // 64 rows x 16 float4 (64 k-values), swizzled
    __shared__ float4 Ws[1024];   // 64 k-rows x 16 float4 (64 h), swizzled

    const int tid = threadIdx.x;
    const int tx = tid & 15, ty = tid >> 4;
    const int row0 = blockIdx.x * 64;

    float accQ[4][4] = {}, accK[4][4] = {}, accV[4][4] = {};

    const float4* x4  = (const float4*)x;   // row stride 128 float4
    const float4* Wq4 = (const float4*)Wq;  // row stride 16 float4
    const float4* Wk4 = (const float4*)Wk;
    const float4* Wv4 = (const float4*)Wv;

    for (int kb = 0; kb < 8; ++kb) {
        __syncthreads();  // previous iteration done reading Xs/Ws
        load_tile(Xs, x4 + (size_t)row0 * 128 + kb * 16, 128, tid);
        load_tile(Ws, Wq4 + (size_t)kb * 1024, 16, tid);
        __syncthreads();
        gemm_tile(accQ, Xs, Ws, tx, ty);
        __syncthreads();
        load_tile(Ws, Wk4 + (size_t)kb * 1024, 16, tid);
        __syncthreads();
        gemm_tile(accK, Xs, Ws, tx, ty);
        __syncthreads();
        load_tile(Ws, Wv4 + (size_t)kb * 1024, 16, tid);
        __syncthreads();
        gemm_tile(accV, Xs, Ws, tx, ty);
    }

    const float4 bqv = ((const float4*)bq)[tx];
    const float4 bkv = ((const float4*)bk)[tx];
    const float4 bvv = ((const float4*)bv)[tx];

    float4* q4 = (float4*)g_q;
    float4* k4 = (float4*)g_k;
    float4* v4 = (float4*)g_v;
#pragma unroll
    for (int i = 0; i < 4; ++i) {
        size_t off = (size_t)(row0 + 4 * ty + i) * 16 + tx;
        q4[off] = make_float4(accQ[i][0] + bqv.x, accQ[i][1] + bqv.y,
                              accQ[i][2] + bqv.z, accQ[i][3] + bqv.w);
        k4[off] = make_float4(accK[i][0] + bkv.x, accK[i][1] + bkv.y,
                              accK[i][2] + bkv.z, accK[i][3] + bkv.w);
        v4[off] = make_float4(accV[i][0] + bvv.x, accV[i][1] + bvv.y,
                              accV[i][2] + bvv.z, accV[i][3] + bvv.w);
    }
}

// ---------------------------------------------------------------------------
// Kernel 2: flash attention over the projected Q/K/V.
// Grid: (64 q-tiles, 4 batches) = 256 blocks. Block: 256 threads.
// Static smem exactly 48 KB: Q, K(/P overlay), V tiles.
// ---------------------------------------------------------------------------
__global__ void __launch_bounds__(256, 2) attn_kernel(float* __restrict__ out)
{
    __shared__ float4 Qs[1024];
    __shared__ float4 Ks[1024];   // K tile; overlaid with P after GEMM1
    __shared__ float4 Vs[1024];

    const int tid = threadIdx.x;
    const int tx = tid & 15, ty = tid >> 4;
    const int b = blockIdx.y;
    const int q0 = blockIdx.x * 64;

    const float4* q4     = (const float4*)g_q + (size_t)(b * SS + q0) * 16;
    const float4* k4base = (const float4*)g_k + (size_t)b * SS * 16;
    const float4* v4base = (const float4*)g_v + (size_t)b * SS * 16;

    // Load Q tile, pre-scaled by 1/sqrt(H) = 0.125 (folds the score scale).
#pragma unroll
    for (int l = 0; l < 4; ++l) {
        int idx = tid + l * 256;
        int r = idx >> 4, c4 = idx & 15;
        float4 v = q4[(size_t)r * 16 + c4];
        v.x *= 0.125f; v.y *= 0.125f; v.z *= 0.125f; v.w *= 0.125f;
        Qs[swz(r, c4)] = v;
    }

    float m[4], lsum[4], o[4][4] = {};
#pragma unroll
    for (int i = 0; i < 4; ++i) { m[i] = -1e30f; lsum[i] = 0.f; }

    for (int kt = 0; kt < 64; ++kt) {
        __syncthreads();  // previous GEMM2 done reading Ks(P)/Vs
        load_tile(Ks, k4base + (size_t)kt * 1024, 16, tid);
        load_tile(Vs, v4base + (size_t)kt * 1024, 16, tid);
        __syncthreads();

        // GEMM1: s[r][c] = sum_d Qs[r][d] * Ks[c][d]   (both K-major)
        float s[4][4] = {};
#pragma unroll 4
        for (int d4 = 0; d4 < 16; ++d4) {
            float4 qv[4];
#pragma unroll
            for (int i = 0; i < 4; ++i) qv[i] = Qs[swz(4 * ty + i, d4)];
#pragma unroll
            for (int j = 0; j < 4; ++j) {
                float4 kv = Ks[swz(4 * tx + j, d4)];
#pragma unroll
                for (int i = 0; i < 4; ++i) {
                    s[i][j] += qv[i].x * kv.x;
                    s[i][j] += qv[i].y * kv.y;
                    s[i][j] += qv[i].z * kv.z;
                    s[i][j] += qv[i].w * kv.w;
                }
            }
        }

        // Online softmax (rows owned by 16 lanes with the same ty -> width-16 shuffles).
#pragma unroll
        for (int i = 0; i < 4; ++i) {
            float mx = fmaxf(fmaxf(s[i][0], s[i][1]), fmaxf(s[i][2], s[i][3]));
#pragma unroll
            for (int off = 8; off; off >>= 1)
                mx = fmaxf(mx, __shfl_xor_sync(0xffffffffu, mx, off, 16));
            float mn = fmaxf(m[i], mx);
            float alpha = __expf(m[i] - mn);
            m[i] = mn;
            float ls = 0.f;
#pragma unroll
            for (int j = 0; j < 4; ++j) {
                float p = __expf(s[i][j] - mn);
                s[i][j] = p;
                ls += p;
            }
#pragma unroll
            for (int off = 8; off; off >>= 1)
                ls += __shfl_xor_sync(0xffffffffu, ls, off, 16);
            lsum[i] = lsum[i] * alpha + ls;
#pragma unroll
            for (int j = 0; j < 4; ++j) o[i][j] *= alpha;
        }

        __syncthreads();  // everyone done reading Ks before P overlay
#pragma unroll
        for (int i = 0; i < 4; ++i)
            Ks[swz(4 * ty + i, tx)] = make_float4(s[i][0], s[i][1], s[i][2], s[i][3]);
        __syncthreads();

        // GEMM2: o[r][h] += sum_c P[r][c] * V[c][h]
        gemm_tile(o, Ks, Vs, tx, ty);
    }

    float4* out4 = (float4*)out + (size_t)(b * SS + q0) * 16;
#pragma unroll
    for (int i = 0; i < 4; ++i) {
        float inv = 1.0f / lsum[i];
        out4[(size_t)(4 * ty + i) * 16 + tx] =
            make_float4(o[i][0] * inv, o[i][1] * inv, o[i][2] * inv, o[i][3] * inv);
    }
}

extern "C" void kernel_launch(void* const* d_in, const int* in_sizes, int n_in,
                              void* d_out, int out_size) {
    (void)in_sizes; (void)n_in; (void)out_size;
    const float* x  = (const float*)d_in[0];
    const float* Wq = (const float*)d_in[1];
    const float* bq = (const float*)d_in[2];
    const float* Wk = (const float*)d_in[3];
    const float* bk = (const float*)d_in[4];
    const float* Wv = (const float*)d_in[5];
    const float* bv = (const float*)d_in[6];

    qkv_kernel<<<256, 256>>>(x, Wq, bq, Wk, bk, Wv, bv);
    attn_kernel<<<dim3(64, 4), 256>>>((float*)d_out);
}

// round 2
// speedup vs baseline: 1.0295x; 1.0295x over previous
#include <cuda_runtime.h>
#include <cuda_bf16.h>

#define BB 4
#define SS 4096
#define DD 512
#define HH 64

typedef unsigned long long u64;

// Scratch for projected Q, K, V: [B*S, 64] each (4 MB each, 12 MB total).
__device__ float g_q[BB * SS * HH];
__device__ float g_k[BB * SS * HH];
__device__ float g_v[BB * SS * HH];

// ---- packed f32x2 helpers (FFMA2 path; only reachable via PTX) -------------
__device__ __forceinline__ u64 dup2(float x) {
    u64 r; asm("mov.b64 %0, {%1, %1};" : "=l"(r) : "f"(x)); return r;
}
__device__ __forceinline__ float2 unpk2(u64 p) {
    float2 v; asm("mov.b64 {%0, %1}, %2;" : "=f"(v.x), "=f"(v.y) : "l"(p)); return v;
}
__device__ __forceinline__ void fma2(u64& d, u64 a, u64 b) {
    asm("fma.rn.f32x2 %0, %1, %2, %0;" : "+l"(d) : "l"(a), "l"(b));
}
__device__ __forceinline__ void mul2(u64& d, u64 a) {
    asm("mul.rn.f32x2 %0, %0, %1;" : "+l"(d) : "l"(a));
}

// XOR swizzle on float4 granularity: 64-row x 16-float4 tile, conflict-free.
__device__ __forceinline__ int swz(int r, int c4) {
    return (r << 4) | (c4 ^ ((r >> 2) & 7));
}

__device__ __forceinline__ float comp4(const float4& v, int cc) {
    return cc == 0 ? v.x : cc == 1 ? v.y : cc == 2 ? v.z : v.w;
}

// Load a 64-row x 16-float4 tile into swizzled smem (256 threads, coalesced).
__device__ __forceinline__ void load_tile(float4* __restrict__ dst,
                                          const float4* __restrict__ src,
                                          int rs4, int tid) {
#pragma unroll
    for (int l = 0; l < 4; ++l) {
        int idx = tid + l * 256;
        int r = idx >> 4, c4 = idx & 15;
        dst[swz(r, c4)] = src[(size_t)r * rs4 + c4];
    }
}

// acc2[i][0] = packed cols(0,1), acc2[i][1] = packed cols(2,3).
// acc += A_tile[64x64] * W_tile[64x64], broadcast A-scalar via dup2.
__device__ __forceinline__ void gemm_tile2(u64 (&acc)[4][2],
                                           const float4* __restrict__ A,
                                           const float4* __restrict__ Wt,
                                           int tx, int ty) {
    const ulonglong2* __restrict__ W2 = (const ulonglong2*)Wt;
#pragma unroll 4
    for (int k4 = 0; k4 < 16; ++k4) {
        float4 a[4];
#pragma unroll
        for (int i = 0; i < 4; ++i) a[i] = A[swz(4 * ty + i, k4)];
#pragma unroll
        for (int cc = 0; cc < 4; ++cc) {
            ulonglong2 w = W2[swz(4 * k4 + cc, tx)];
#pragma unroll
            for (int i = 0; i < 4; ++i) {
                u64 av = dup2(comp4(a[i], cc));
                fma2(acc[i][0], av, w.x);
                fma2(acc[i][1], av, w.y);
            }
        }
    }
}

// ---------------------------------------------------------------------------
// Kernel 1: fused QKV projection. 256 blocks x 256 threads.
// ---------------------------------------------------------------------------
__global__ void __launch_bounds__(256, 2) qkv_kernel(
    const float* __restrict__ x,
    const float* __restrict__ Wq, const float* __restrict__ bq,
    const float* __restrict__ Wk, const float* __restrict__ bk,
    const float* __restrict__ Wv, const float* __restrict__ bv)
{
    __shared__ float4 Xs[1024];
    __shared__ float4 Ws[1024];

    const int tid = threadIdx.x;
    const int tx = tid & 15, ty = tid >> 4;
    const int row0 = blockIdx.x * 64;

    u64 accQ[4][2] = {}, accK[4][2] = {}, accV[4][2] = {};

    const float4* x4  = (const float4*)x;
    const float4* Wq4 = (const float4*)Wq;
    const float4* Wk4 = (const float4*)Wk;
    const float4* Wv4 = (const float4*)Wv;

    for (int kb = 0; kb < 8; ++kb) {
        __syncthreads();
        load_tile(Xs, x4 + (size_t)row0 * 128 + kb * 16, 128, tid);
        load_tile(Ws, Wq4 + (size_t)kb * 1024, 16, tid);
        __syncthreads();
        gemm_tile2(accQ, Xs, Ws, tx, ty);
        __syncthreads();
        load_tile(Ws, Wk4 + (size_t)kb * 1024, 16, tid);
        __syncthreads();
        gemm_tile2(accK, Xs, Ws, tx, ty);
        __syncthreads();
        load_tile(Ws, Wv4 + (size_t)kb * 1024, 16, tid);
        __syncthreads();
        gemm_tile2(accV, Xs, Ws, tx, ty);
    }

    const float4 bqv = ((const float4*)bq)[tx];
    const float4 bkv = ((const float4*)bk)[tx];
    const float4 bvv = ((const float4*)bv)[tx];

    float4* q4 = (float4*)g_q;
    float4* k4 = (float4*)g_k;
    float4* v4 = (float4*)g_v;
#pragma unroll
    for (int i = 0; i < 4; ++i) {
        size_t off = (size_t)(row0 + 4 * ty + i) * 16 + tx;
        float2 q01 = unpk2(accQ[i][0]), q23 = unpk2(accQ[i][1]);
        float2 k01 = unpk2(accK[i][0]), k23 = unpk2(accK[i][1]);
        float2 v01 = unpk2(accV[i][0]), v23 = unpk2(accV[i][1]);
        q4[off] = make_float4(q01.x + bqv.x, q01.y + bqv.y, q23.x + bqv.z, q23.y + bqv.w);
        k4[off] = make_float4(k01.x + bkv.x, k01.y + bkv.y, k23.x + bkv.z, k23.y + bkv.w);
        v4[off] = make_float4(v01.x + bvv.x, v01.y + bvv.y, v23.x + bvv.z, v23.y + bvv.w);
    }
}

// ---------------------------------------------------------------------------
// Kernel 2: flash attention. Grid (64,4) x 256 threads, 48 KB static smem.
// ---------------------------------------------------------------------------
__global__ void __launch_bounds__(256, 2) attn_kernel(float* __restrict__ out)
{
    __shared__ float4 Qs[1024];
    __shared__ float4 Ks[1024];   // K tile; overlaid with P after softmax
    __shared__ float4 Vs[1024];

    const int tid = threadIdx.x;
    const int tx = tid & 15, ty = tid >> 4;
    const int b = blockIdx.y;
    const int q0 = blockIdx.x * 64;

    const float4* q4     = (const float4*)g_q + (size_t)(b * SS + q0) * 16;
    const float4* k4base = (const float4*)g_k + (size_t)b * SS * 16;
    const float4* v4base = (const float4*)g_v + (size_t)b * SS * 16;

    // Load Q tile, pre-scaled by 1/sqrt(64) = 0.125.
#pragma unroll
    for (int l = 0; l < 4; ++l) {
        int idx = tid + l * 256;
        int r = idx >> 4, c4 = idx & 15;
        float4 v = q4[(size_t)r * 16 + c4];
        v.x *= 0.125f; v.y *= 0.125f; v.z *= 0.125f; v.w *= 0.125f;
        Qs[swz(r, c4)] = v;
    }

    float m[4], lsum[4];
    u64 o2[4][2] = {};
#pragma unroll
    for (int i = 0; i < 4; ++i) { m[i] = -1e30f; lsum[i] = 0.f; }

    const ulonglong2* __restrict__ Q2 = (const ulonglong2*)Qs;
    const ulonglong2* __restrict__ K2 = (const ulonglong2*)Ks;

    for (int kt = 0; kt < 64; ++kt) {
        __syncthreads();
        load_tile(Ks, k4base + (size_t)kt * 1024, 16, tid);
        load_tile(Vs, v4base + (size_t)kt * 1024, 16, tid);
        __syncthreads();

        // GEMM1: packed partial dot products along the head dim.
        u64 s2[4][4] = {};
#pragma unroll 4
        for (int d4 = 0; d4 < 16; ++d4) {
            ulonglong2 q[4];
#pragma unroll
            for (int i = 0; i < 4; ++i) q[i] = Q2[swz(4 * ty + i, d4)];
#pragma unroll
            for (int j = 0; j < 4; ++j) {
                ulonglong2 k = K2[swz(4 * tx + j, d4)];
#pragma unroll
                for (int i = 0; i < 4; ++i) {
                    fma2(s2[i][j], q[i].x, k.x);
                    fma2(s2[i][j], q[i].y, k.y);
                }
            }
        }

        // Horizontal add of packed halves -> scalar scores.
        float s[4][4];
#pragma unroll
        for (int i = 0; i < 4; ++i)
#pragma unroll
            for (int j = 0; j < 4; ++j) {
                float2 p = unpk2(s2[i][j]);
                s[i][j] = p.x + p.y;
            }

        // Online softmax (16-lane row groups).
#pragma unroll
        for (int i = 0; i < 4; ++i) {
            float mx = fmaxf(fmaxf(s[i][0], s[i][1]), fmaxf(s[i][2], s[i][3]));
#pragma unroll
            for (int off = 8; off; off >>= 1)
                mx = fmaxf(mx, __shfl_xor_sync(0xffffffffu, mx, off, 16));
            float mn = fmaxf(m[i], mx);
            float alpha = __expf(m[i] - mn);
            m[i] = mn;
            float ls = 0.f;
#pragma unroll
            for (int j = 0; j < 4; ++j) {
                float p = __expf(s[i][j] - mn);
                s[i][j] = p;
                ls += p;
            }
#pragma unroll
            for (int off = 8; off; off >>= 1)
                ls += __shfl_xor_sync(0xffffffffu, ls, off, 16);
            lsum[i] = lsum[i] * alpha + ls;
            u64 a2 = dup2(alpha);
            mul2(o2[i][0], a2);
            mul2(o2[i][1], a2);
        }

        __syncthreads();  // done reading Ks as K before P overlay
#pragma unroll
        for (int i = 0; i < 4; ++i)
            Ks[swz(4 * ty + i, tx)] = make_float4(s[i][0], s[i][1], s[i][2], s[i][3]);
        __syncthreads();

        // GEMM2: O += P * V (packed over the 4 head-dim cols this thread owns).
        gemm_tile2(o2, Ks, Vs, tx, ty);
    }

    float4* out4 = (float4*)out + (size_t)(b * SS + q0) * 16;
#pragma unroll
    for (int i = 0; i < 4; ++i) {
        float inv = 1.0f / lsum[i];
        float2 o01 = unpk2(o2[i][0]), o23 = unpk2(o2[i][1]);
        out4[(size_t)(4 * ty + i) * 16 + tx] =
            make_float4(o01.x * inv, o01.y * inv, o23.x * inv, o23.y * inv);
    }
}

extern "C" void kernel_launch(void* const* d_in, const int* in_sizes, int n_in,
                              void* d_out, int out_size) {
    (void)in_sizes; (void)n_in; (void)out_size;
    const float* x  = (const float*)d_in[0];
    const float* Wq = (const float*)d_in[1];
    const float* bq = (const float*)d_in[2];
    const float* Wk = (const float*)d_in[3];
    const float* bk = (const float*)d_in[4];
    const float* Wv = (const float*)d_in[5];
    const float* bv = (const float*)d_in[6];

    qkv_kernel<<<256, 256>>>(x, Wq, bq, Wk, bk, Wv, bv);
    attn_kernel<<<dim3(64, 4), 256>>>((float*)d_out);
}